// round 16
// baseline (speedup 1.0000x reference)
#include <cuda_runtime.h>
#include <cstdint>

// FlowNetC correlation: out[b, (dy+4)*9+(dx+4), y, x] =
//   (1/C) * sum_c in1[b,c,y,x] * in2[b,c,y+dy,x+dx], zero-padded.
// Shapes: in1,in2 [8,256,96,128] f32; out [8,81,96,128] f32.
//
// R16: NO shared memory. Block = 12 warps = (dyl 0..2) x (row 0..3), 384 thr.
// Warp (row,dyl) computes out row y0+row for dy = 3*dygrp+dyl-4.
// Per channel: LDG.128 in1 (shared across dyl -> L1 hits), LDG.128 in2 row,
// halo via 8x shfl_sync (lane+-1); lane-edge cells are the x-pads -> SEL 0.
// Out-of-range in2 rows: whole warp's 9 out channels are zero -> store, exit.
// Removes all LDS/STS/cp.async traffic: L1 wavefronts/chunk drop ~2.5x,
// leaving the FFMA pipe as the binding resource.

#define B_   8
#define C_   256
#define H_   96
#define W_   128
#define HW_  (H_ * W_)
#define CC   4      // channels per unrolled step (8 LDGs in flight)
#define RWS  4      // output rows per block

__global__ __launch_bounds__(384, 2) void corr_kernel(
    const float* __restrict__ in1,
    const float* __restrict__ in2,
    float* __restrict__ out)
{
    const int dygrp = blockIdx.x;       // 0..2 -> dy = 3*dygrp + dyl - 4
    const int y0    = blockIdx.y * RWS;
    const int b     = blockIdx.z;
    const int tid   = threadIdx.x;
    const int wid   = tid >> 5;         // 0..11
    const int lane  = tid & 31;
    const int dyl   = wid >> 2;         // 0..2
    const int row   = wid & 3;          // 0..3
    const int x0    = lane << 2;        // 0..124
    const int dyi   = 3 * dygrp + dyl;  // 0..8
    const int y2    = y0 + row + dyi - 4;

    const float sc = 1.0f / (float)C_;
    float* ob = out + (((long)b * 81 + dyi * 9) * H_ + (y0 + row)) * (long)W_ + x0;

    // Out-of-range in2 row: contribution is zero for all 9 dx channels.
    if ((unsigned)y2 >= (unsigned)H_) {
        float4 z = make_float4(0.f, 0.f, 0.f, 0.f);
#pragma unroll
        for (int d = 0; d < 9; d++)
            *reinterpret_cast<float4*>(ob + (long)d * HW_) = z;
        return;
    }

    float acc[4][9];
#pragma unroll
    for (int i = 0; i < 4; i++)
#pragma unroll
        for (int d = 0; d < 9; d++) acc[i][d] = 0.0f;

    const float* a_run = in1 + ((long)(b * C_)) * HW_ + (long)(y0 + row) * W_ + x0;
    const float* v_run = in2 + ((long)(b * C_)) * HW_ + (long)y2 * W_ + x0;

    const bool l_edge = (lane == 0);
    const bool r_edge = (lane == 31);

    for (int c0 = 0; c0 < C_; c0 += CC) {
#pragma unroll
        for (int cc = 0; cc < CC; cc++) {
            float4 a = *reinterpret_cast<const float4*>(a_run + (long)cc * HW_);
            float4 v = *reinterpret_cast<const float4*>(v_run + (long)cc * HW_);

            // halo via shuffles: left = lane-1's v (x0-4..x0-1),
            //                    right = lane+1's v (x0+4..x0+7)
            float l0 = __shfl_up_sync(0xffffffffu, v.x, 1);
            float l1 = __shfl_up_sync(0xffffffffu, v.y, 1);
            float l2 = __shfl_up_sync(0xffffffffu, v.z, 1);
            float l3 = __shfl_up_sync(0xffffffffu, v.w, 1);
            float r0 = __shfl_down_sync(0xffffffffu, v.x, 1);
            float r1 = __shfl_down_sync(0xffffffffu, v.y, 1);
            float r2 = __shfl_down_sync(0xffffffffu, v.z, 1);
            float r3 = __shfl_down_sync(0xffffffffu, v.w, 1);
            if (l_edge) { l0 = 0.f; l1 = 0.f; l2 = 0.f; l3 = 0.f; }   // x < 0
            if (r_edge) { r0 = 0.f; r1 = 0.f; r2 = 0.f; r3 = 0.f; }   // x >= W

            float w[12] = {l0, l1, l2, l3,
                           v.x, v.y, v.z, v.w,
                           r0, r1, r2, r3};
            float av[4] = {a.x, a.y, a.z, a.w};
#pragma unroll
            for (int i = 0; i < 4; i++)
#pragma unroll
                for (int d = 0; d < 9; d++)
                    acc[i][d] = fmaf(av[i], w[i + d], acc[i][d]);
        }
        a_run += (long)CC * HW_;
        v_run += (long)CC * HW_;
    }

    // ---- epilogue: 9 float4 stores ----
#pragma unroll
    for (int d = 0; d < 9; d++) {
        float4 o = make_float4(acc[0][d] * sc, acc[1][d] * sc,
                               acc[2][d] * sc, acc[3][d] * sc);
        *reinterpret_cast<float4*>(ob + (long)d * HW_) = o;
    }
}

extern "C" void kernel_launch(void* const* d_in, const int* in_sizes, int n_in,
                              void* d_out, int out_size)
{
    const float* in1 = (const float*)d_in[0];
    const float* in2 = (const float*)d_in[1];
    float* out = (float*)d_out;

    dim3 grid(3, H_ / RWS, B_);   // dy-group, y-tiles, batch
    dim3 block(384);              // 12 warps = 3 dy x 4 rows
    corr_kernel<<<grid, block>>>(in1, in2, out);
}